// round 12
// baseline (speedup 1.0000x reference)
#include <cuda_runtime.h>

// MorphologicalDegradation, i=30 fixed: k=7 circular SE, dilation, weight=0.24.
//   out = clip(0.76*x + 0.24*(1 - prod_taps(1 - x_shift)), 0, 1)
// Row decomposition (half-widths by dy): {0,2,2,3,2,2,0}:
//   out(s) = f( t(s-3) * h2(s-2) * h2(s-1) * h3(s) * h2(s+1) * h2(s+2) * t(s+3) )
// With G'(r) = h2(r-1)*h2(r):  out(s) = t(s-3) * G'(s-1) * h3(s) * G'(s+2) * t(s+3)
//
// R12 (base = R9/R11): ring-4 accumulators + exact compile-time liveness.
// ROUT=4 -> at most 4 outputs pending -> acc[4] (slot = s&3), -12 regs.
// Stage/h2/h3/shuffle work only in its live window (ii is an unroll constant):
//   init ii in [0,3]; G'(s=r+1) [2,5]; h3 [3,6]; G'(s=r-2) [5,8]; emit [6,9];
//   h2/shuffles/halo loads [1,8].  Single instantiation (R6's regression came
// from dual EDGE/interior code bloat, not the trim itself).
// Keep: 8192 warps (2048 x 128-thr blocks), depth-3 center prefetch, shuffle
// halos (each pixel loaded once), __stcs stores, pairwise horiz products.

static constexpr int Hh     = 512;
static constexpr int Ww     = 512;
static constexpr int ROUT   = 4;             // output rows per warp-chunk
static constexpr int CHUNKS = 128;           // 512/4
static constexpr int ITERS  = ROUT + 6;      // 10 input rows streamed

__device__ __forceinline__ float4 zero4() { return make_float4(0.f, 0.f, 0.f, 0.f); }

__global__ void __launch_bounds__(128, 8)
morph_kernel(const float* __restrict__ x, float* __restrict__ out)
{
    const int gt    = blockIdx.x * 128 + threadIdx.x;
    const int gw    = gt >> 5;            // global warp id, 0..8191
    const int ln    = gt & 31;
    const int wp    = gw & 3;             // column quadrant (128 cols each)
    const int gwq   = gw >> 2;            // 0..2047
    const int chunk = gwq & (CHUNKS - 1); // row chunk
    const int img   = gwq >> 7;           // 16 images

    const int c0 = wp * 128 + ln * 4;     // first of 4 owned columns
    const int y0 = chunk * ROUT;

    const float* base  = x   + img * (Hh * Ww);
    float*       obase = out + img * (Hh * Ww);

    const float WGT  = 0.24f;
    const float IWGT = 1.0f - 0.24f;

    const bool laneL = (ln == 0)  && (c0 >= 4);          // left warp-boundary load
    const bool laneR = (ln == 31) && (c0 + 4 <= Ww - 4); // right warp-boundary load

    float4 acc[4];   // ring of pending outputs, slot = s & 3

    auto loadM = [&](int ii) -> float4 {
        const int r = y0 - 3 + ii;
        return ((unsigned)r < (unsigned)Hh)
            ? __ldg((const float4*)(base + r * Ww + c0)) : zero4();
    };

    // center-row pipeline, depth 3 (~3 loop bodies >= L2 hit latency)
    float4 M0 = loadM(0);
    float4 M1 = loadM(1);
    float4 M2 = loadM(2);

    // previous row's h2 (for G' = h2_prev * h2)
    float hp0 = 1.f, hp1 = 1.f, hp2 = 1.f, hp3 = 1.f;

#pragma unroll
    for (int ii = 0; ii < ITERS; ++ii) {
        const int r = y0 - 3 + ii;

        // compile-time liveness windows (ii is an unroll constant)
        const bool liveInit = (ii <= 3);                  // s = r+3
        const bool liveGp1  = (ii >= 2) && (ii <= 5);     // G' for s = r+1
        const bool liveH3   = (ii >= 3) && (ii <= 6);     // h3 for s = r
        const bool liveGm2  = (ii >= 5) && (ii <= 8);     // G' for s = r-2
        const bool liveEmit = (ii >= 6);                  // s = r-3
        const bool needH2   = (ii >= 1) && (ii <= 8);     // h2(r) used now or as hp next
        const bool needG    = liveGp1 || liveGm2;

        // prefetch center row at depth 3
        float4 Mnew = (ii + 3 < ITERS) ? loadM(ii + 3) : zero4();

        // warp-boundary halos: 1-lane predicated loads (current row, only if h2 needed)
        float4 Lh = zero4(), Rh = zero4();
        if (needH2 && laneL && (unsigned)r < (unsigned)Hh)
            Lh = __ldg((const float4*)(base + r * Ww + c0 - 4));
        if (needH2 && laneR && (unsigned)r < (unsigned)Hh)
            Rh = __ldg((const float4*)(base + r * Ww + c0 + 4));

        // reload raw x for the emit row early (L1 hit; loaded 3 iters ago).
        // y = y0+ii-6 in [y0, y0+3] subset [0,511] -> no bounds check needed.
        const int y = y0 + ii - 6;
        float4 xv;
        if (liveEmit) xv = __ldg((const float4*)(base + y * Ww + c0));

        // own t-values (cols c0..c0+3)
        const float tm0 = 1.f - M0.x, tm1 = 1.f - M0.y, tm2 = 1.f - M0.z, tm3 = 1.f - M0.w;

        float h2[4], h3[4];
        if (needH2) {
            // halo t-values from neighbor lanes
            float t1 = __shfl_up_sync(0xffffffffu, tm1, 1);   // t(c0-3)
            float t2 = __shfl_up_sync(0xffffffffu, tm2, 1);   // t(c0-2)
            float t3 = __shfl_up_sync(0xffffffffu, tm3, 1);   // t(c0-1)
            float t8 = __shfl_down_sync(0xffffffffu, tm0, 1); // t(c0+4)
            float t9 = __shfl_down_sync(0xffffffffu, tm1, 1); // t(c0+5)
            float t10= __shfl_down_sync(0xffffffffu, tm2, 1); // t(c0+6)
            if (ln == 0)  { t1 = 1.f - Lh.y; t2 = 1.f - Lh.z; t3 = 1.f - Lh.w; }
            if (ln == 31) { t8 = 1.f - Rh.x; t9 = 1.f - Rh.y; t10 = 1.f - Rh.z; }
            // (image-edge lanes: Lh/Rh stay zero -> t = 1, matching zero-pad)

            const float t4 = tm0, t5 = tm1, t6 = tm2, t7 = tm3;

            // pairwise-shared horizontal products
            const float p23 = t2 * t3, p45 = t4 * t5, p67 = t6 * t7, p89 = t8 * t9;
            h2[0] = p23 * p45 * t6;       // t2 t3 t4 t5 t6
            h2[1] = t3  * p45 * p67;      // t3 t4 t5 t6 t7
            h2[2] = p45 * p67 * t8;       // t4 t5 t6 t7 t8
            h2[3] = t5  * p67 * p89;      // t5 t6 t7 t8 t9
            if (liveH3) {
                h3[0] = h2[0] * t1 * t7;
                h3[1] = h2[1] * t2 * t8;
                h3[2] = h2[2] * t3 * t9;
                h3[3] = h2[3] * t4 * t10;
            }
        }

        // paired vertical factor: G'(r) = h2(r-1) * h2(r)
        float g0, g1, g2, g3;
        if (needG) {
            g0 = hp0 * h2[0]; g1 = hp1 * h2[1]; g2 = hp2 * h2[2]; g3 = hp3 * h2[3];
        }
        if (needH2) { hp0 = h2[0]; hp1 = h2[1]; hp2 = h2[2]; hp3 = h2[3]; }

        // ring stages, slot = s & 3 (static after unroll)
        if (liveInit)                                 // s = r+3 = y0+ii
            acc[(y0 + ii) & 3] = make_float4(tm0, tm1, tm2, tm3);
        if (liveGp1) { float4& a = acc[(y0 + ii - 2) & 3];   // s = r+1
            a.x *= g0; a.y *= g1; a.z *= g2; a.w *= g3; }
        if (liveH3)  { float4& a = acc[(y0 + ii - 3) & 3];   // s = r
            a.x *= h3[0]; a.y *= h3[1]; a.z *= h3[2]; a.w *= h3[3]; }
        if (liveGm2) { float4& a = acc[(y0 + ii - 5) & 3];   // s = r-2
            a.x *= g0; a.y *= g1; a.z *= g2; a.w *= g3; }

        if (liveEmit) {                               // s = r-3 = y
            float4 a = acc[y & 3];
            a.x *= tm0; a.y *= tm1; a.z *= tm2; a.w *= tm3;

            float4 o;
            float m;
            m   = 1.f - a.x;   // a in [0,1] -> m in [0,1], no extra clip needed
            o.x = fminf(fmaxf(IWGT * xv.x + WGT * m, 0.f), 1.f);
            m   = 1.f - a.y;
            o.y = fminf(fmaxf(IWGT * xv.y + WGT * m, 0.f), 1.f);
            m   = 1.f - a.z;
            o.z = fminf(fmaxf(IWGT * xv.z + WGT * m, 0.f), 1.f);
            m   = 1.f - a.w;
            o.w = fminf(fmaxf(IWGT * xv.w + WGT * m, 0.f), 1.f);

            __stcs((float4*)(obase + y * Ww + c0), o);   // streaming store
        }

        M0 = M1; M1 = M2; M2 = Mnew;
    }
}

extern "C" void kernel_launch(void* const* d_in, const int* in_sizes, int n_in,
                              void* d_out, int out_size)
{
    (void)in_sizes; (void)n_in; (void)out_size;
    const float* x = (const float*)d_in[0];   // (16,1,512,512) fp32; d_in[1] = i (fixed 30)
    float* o = (float*)d_out;
    // 8192 warps = 16 imgs * 128 row-chunks * 4 column-quadrants
    // 2048 blocks of 128 threads (8 resident blocks/SM)
    morph_kernel<<<2048, 128>>>(x, o);
}

// round 13
// speedup vs baseline: 1.0060x; 1.0060x over previous
#include <cuda_runtime.h>

// MorphologicalDegradation, i=30 fixed: k=7 circular SE, dilation, weight=0.24.
//   out = clip(0.76*x + 0.24*(1 - prod_taps(1 - x_shift)), 0, 1)
// Row decomposition (half-widths by dy): {0,2,2,3,2,2,0}:
//   out(s) = f( t(s-3) * h2(s-2) * h2(s-1) * h3(s) * h2(s+1) * h2(s+2) * t(s+3) )
// With G'(r) = h2(r-1)*h2(r):  out(s) = t(s-3) * G'(s-1) * h3(s) * G'(s+2) * t(s+3)
//
// R13 (base = R12, best ncu 10.37us): wave quantization + deeper prefetch.
//  (1) __launch_bounds__(128,7): 7 blocks/SM -> 1036 resident slots ->
//      2048 blocks = 1.977 ~ 2 EXACT waves (R12 ran 1.73 ragged waves,
//      achieved occ 25/32 warps). Reg cap rises 64 -> 72.
//  (2) M-prefetch depth 3 -> 4 with the freed registers (lookahead ~4 bodies
//      > L2 hit latency 234-262cyc at steady state).
// Keep: ring-4 accumulators + compile-time liveness, 8192 warps, shuffle
// halos (each pixel loaded once), __stcs stores, pairwise products, G'.

static constexpr int Hh     = 512;
static constexpr int Ww     = 512;
static constexpr int ROUT   = 4;             // output rows per warp-chunk
static constexpr int CHUNKS = 128;           // 512/4
static constexpr int ITERS  = ROUT + 6;      // 10 input rows streamed
static constexpr int PDEPTH = 4;             // M-prefetch depth

__device__ __forceinline__ float4 zero4() { return make_float4(0.f, 0.f, 0.f, 0.f); }

__global__ void __launch_bounds__(128, 7)
morph_kernel(const float* __restrict__ x, float* __restrict__ out)
{
    const int gt    = blockIdx.x * 128 + threadIdx.x;
    const int gw    = gt >> 5;            // global warp id, 0..8191
    const int ln    = gt & 31;
    const int wp    = gw & 3;             // column quadrant (128 cols each)
    const int gwq   = gw >> 2;            // 0..2047
    const int chunk = gwq & (CHUNKS - 1); // row chunk
    const int img   = gwq >> 7;           // 16 images

    const int c0 = wp * 128 + ln * 4;     // first of 4 owned columns
    const int y0 = chunk * ROUT;

    const float* base  = x   + img * (Hh * Ww);
    float*       obase = out + img * (Hh * Ww);

    const float WGT  = 0.24f;
    const float IWGT = 1.0f - 0.24f;

    const bool laneL = (ln == 0)  && (c0 >= 4);          // left warp-boundary load
    const bool laneR = (ln == 31) && (c0 + 4 <= Ww - 4); // right warp-boundary load

    float4 acc[4];   // ring of pending outputs, slot = s & 3

    auto loadM = [&](int ii) -> float4 {
        const int r = y0 - 3 + ii;
        return ((unsigned)r < (unsigned)Hh)
            ? __ldg((const float4*)(base + r * Ww + c0)) : zero4();
    };

    // center-row pipeline, depth 4
    float4 Mp[PDEPTH];
    Mp[0] = loadM(0);
    Mp[1] = loadM(1);
    Mp[2] = loadM(2);
    Mp[3] = loadM(3);

    // previous row's h2 (for G' = h2_prev * h2)
    float hp0 = 1.f, hp1 = 1.f, hp2 = 1.f, hp3 = 1.f;

#pragma unroll
    for (int ii = 0; ii < ITERS; ++ii) {
        const int r = y0 - 3 + ii;

        // compile-time liveness windows (ii is an unroll constant)
        const bool liveInit = (ii <= 3);                  // s = r+3
        const bool liveGp1  = (ii >= 2) && (ii <= 5);     // G' for s = r+1
        const bool liveH3   = (ii >= 3) && (ii <= 6);     // h3 for s = r
        const bool liveGm2  = (ii >= 5) && (ii <= 8);     // G' for s = r-2
        const bool liveEmit = (ii >= 6);                  // s = r-3
        const bool needH2   = (ii >= 1) && (ii <= 8);     // h2(r) used now or as hp next
        const bool needG    = liveGp1 || liveGm2;

        const float4 M0 = Mp[0];

        // prefetch center row at depth PDEPTH
        float4 Mnew = (ii + PDEPTH < ITERS) ? loadM(ii + PDEPTH) : zero4();

        // warp-boundary halos: 1-lane predicated loads (current row, only if h2 needed)
        float4 Lh = zero4(), Rh = zero4();
        if (needH2 && laneL && (unsigned)r < (unsigned)Hh)
            Lh = __ldg((const float4*)(base + r * Ww + c0 - 4));
        if (needH2 && laneR && (unsigned)r < (unsigned)Hh)
            Rh = __ldg((const float4*)(base + r * Ww + c0 + 4));

        // reload raw x for the emit row early (L1 hit; loaded 3 iters ago).
        // y = y0+ii-6 in [y0, y0+3] subset [0,511] -> no bounds check needed.
        const int y = y0 + ii - 6;
        float4 xv;
        if (liveEmit) xv = __ldg((const float4*)(base + y * Ww + c0));

        // own t-values (cols c0..c0+3)
        const float tm0 = 1.f - M0.x, tm1 = 1.f - M0.y, tm2 = 1.f - M0.z, tm3 = 1.f - M0.w;

        float h2[4], h3[4];
        if (needH2) {
            // halo t-values from neighbor lanes
            float t1 = __shfl_up_sync(0xffffffffu, tm1, 1);   // t(c0-3)
            float t2 = __shfl_up_sync(0xffffffffu, tm2, 1);   // t(c0-2)
            float t3 = __shfl_up_sync(0xffffffffu, tm3, 1);   // t(c0-1)
            float t8 = __shfl_down_sync(0xffffffffu, tm0, 1); // t(c0+4)
            float t9 = __shfl_down_sync(0xffffffffu, tm1, 1); // t(c0+5)
            float t10= __shfl_down_sync(0xffffffffu, tm2, 1); // t(c0+6)
            if (ln == 0)  { t1 = 1.f - Lh.y; t2 = 1.f - Lh.z; t3 = 1.f - Lh.w; }
            if (ln == 31) { t8 = 1.f - Rh.x; t9 = 1.f - Rh.y; t10 = 1.f - Rh.z; }
            // (image-edge lanes: Lh/Rh stay zero -> t = 1, matching zero-pad)

            const float t4 = tm0, t5 = tm1, t6 = tm2, t7 = tm3;

            // pairwise-shared horizontal products
            const float p23 = t2 * t3, p45 = t4 * t5, p67 = t6 * t7, p89 = t8 * t9;
            h2[0] = p23 * p45 * t6;       // t2 t3 t4 t5 t6
            h2[1] = t3  * p45 * p67;      // t3 t4 t5 t6 t7
            h2[2] = p45 * p67 * t8;       // t4 t5 t6 t7 t8
            h2[3] = t5  * p67 * p89;      // t5 t6 t7 t8 t9
            if (liveH3) {
                h3[0] = h2[0] * t1 * t7;
                h3[1] = h2[1] * t2 * t8;
                h3[2] = h2[2] * t3 * t9;
                h3[3] = h2[3] * t4 * t10;
            }
        }

        // paired vertical factor: G'(r) = h2(r-1) * h2(r)
        float g0, g1, g2, g3;
        if (needG) {
            g0 = hp0 * h2[0]; g1 = hp1 * h2[1]; g2 = hp2 * h2[2]; g3 = hp3 * h2[3];
        }
        if (needH2) { hp0 = h2[0]; hp1 = h2[1]; hp2 = h2[2]; hp3 = h2[3]; }

        // ring stages, slot = s & 3 (static after unroll)
        if (liveInit)                                 // s = r+3 = y0+ii
            acc[(y0 + ii) & 3] = make_float4(tm0, tm1, tm2, tm3);
        if (liveGp1) { float4& a = acc[(y0 + ii - 2) & 3];   // s = r+1
            a.x *= g0; a.y *= g1; a.z *= g2; a.w *= g3; }
        if (liveH3)  { float4& a = acc[(y0 + ii - 3) & 3];   // s = r
            a.x *= h3[0]; a.y *= h3[1]; a.z *= h3[2]; a.w *= h3[3]; }
        if (liveGm2) { float4& a = acc[(y0 + ii - 5) & 3];   // s = r-2
            a.x *= g0; a.y *= g1; a.z *= g2; a.w *= g3; }

        if (liveEmit) {                               // s = r-3 = y
            float4 a = acc[y & 3];
            a.x *= tm0; a.y *= tm1; a.z *= tm2; a.w *= tm3;

            float4 o;
            float m;
            m   = 1.f - a.x;   // a in [0,1] -> m in [0,1], no extra clip needed
            o.x = fminf(fmaxf(IWGT * xv.x + WGT * m, 0.f), 1.f);
            m   = 1.f - a.y;
            o.y = fminf(fmaxf(IWGT * xv.y + WGT * m, 0.f), 1.f);
            m   = 1.f - a.z;
            o.z = fminf(fmaxf(IWGT * xv.z + WGT * m, 0.f), 1.f);
            m   = 1.f - a.w;
            o.w = fminf(fmaxf(IWGT * xv.w + WGT * m, 0.f), 1.f);

            __stcs((float4*)(obase + y * Ww + c0), o);   // streaming store
        }

        // advance M pipeline
        Mp[0] = Mp[1]; Mp[1] = Mp[2]; Mp[2] = Mp[3]; Mp[3] = Mnew;
    }
}

extern "C" void kernel_launch(void* const* d_in, const int* in_sizes, int n_in,
                              void* d_out, int out_size)
{
    (void)in_sizes; (void)n_in; (void)out_size;
    const float* x = (const float*)d_in[0];   // (16,1,512,512) fp32; d_in[1] = i (fixed 30)
    float* o = (float*)d_out;
    // 8192 warps = 16 imgs * 128 row-chunks * 4 column-quadrants
    // 2048 blocks of 128 threads; 7 blocks/SM residency -> 1036 slots ->
    // 2048/1036 = 1.977 ~ two exact waves
    morph_kernel<<<2048, 128>>>(x, o);
}